// round 5
// baseline (speedup 1.0000x reference)
#include <cuda_runtime.h>
#include <cstdint>

// ---------------------------------------------------------------------------
// AnchorLayer: B=16, A=12, H=W=64 (N=49152 anchors/row), G=64 gt boxes.
// Output (B, A, H, W, 5) = [label, tx, ty, tw, th], float32.
// R2 (resubmit, 4th attempt): branch-free IoU inner loop (inline Markstein
//     division, predicated selects) — removes BSSY/BSYNC + div slow-path
//     machinery from the 50M-pair hot loop.
// ---------------------------------------------------------------------------

#define BB   16
#define NN   49152          // anchors per batch row
#define GG   64
#define TOT  (BB * NN)      // 786432
#define HALF (TOT / 2)
#define SENT 0xFFFFFFFFu

#define TF_PARTITIONABLE 1

__device__ unsigned g_pos, g_neg;
__device__ unsigned g_hist1[BB * 4096];
__device__ unsigned g_hist2[BB * 2048];
__device__ unsigned g_T1[BB], g_C1[BB];
__device__ unsigned g_T2[BB], g_C2[BB];
__device__ unsigned g_key[TOT];   // key23 for negatives, SENT otherwise

// ---------------- threefry-2x32, key = (0, 42) -----------------------------
__device__ __forceinline__ unsigned tf_rotl(unsigned x, int d) {
    return (x << d) | (x >> (32 - d));
}

__device__ __forceinline__ unsigned rand_bits(unsigned i) {
    const unsigned ks0 = 0u, ks1 = 42u, ks2 = 0x1BD11BDAu ^ 0u ^ 42u;
#if TF_PARTITIONABLE
    unsigned x0 = 0u, x1 = i;
#else
    bool lo = i < HALF;
    unsigned x0 = lo ? i : i - HALF;
    unsigned x1 = lo ? i + HALF : i;
#endif
    x0 += ks0; x1 += ks1;
#define TF_R(r) { x0 += x1; x1 = tf_rotl(x1, r); x1 ^= x0; }
    TF_R(13) TF_R(15) TF_R(26) TF_R(6)
    x0 += ks1; x1 += ks2 + 1u;
    TF_R(17) TF_R(29) TF_R(16) TF_R(24)
    x0 += ks2; x1 += ks0 + 2u;
    TF_R(13) TF_R(15) TF_R(26) TF_R(6)
    x0 += ks0; x1 += ks1 + 3u;
    TF_R(17) TF_R(29) TF_R(16) TF_R(24)
    x0 += ks1; x1 += ks2 + 4u;
    TF_R(13) TF_R(15) TF_R(26) TF_R(6)
    x0 += ks2; x1 += ks0 + 5u;
#undef TF_R
#if TF_PARTITIONABLE
    return x0 ^ x1;
#else
    return lo ? x0 : x1;
#endif
}

// Correctly-rounded fp32 division for normal-range operands, branch-free.
// MUFU rcp.approx + 2 Newton iterations (reciprocal to <=0.5 ulp) + Markstein
// final correction => RN(a/b), bit-identical to __fdiv_rn for our inputs
// (b in ~[1, 1100], a in [0, 400]). a==0 -> exactly 0.
__device__ __forceinline__ float exact_div(float a, float b) {
    float r;
    asm("rcp.approx.f32 %0, %1;" : "=f"(r) : "f"(b));
    r = __fmaf_rn(__fmaf_rn(-b, r, 1.0f), r, r);
    r = __fmaf_rn(__fmaf_rn(-b, r, 1.0f), r, r);
    float q = __fmul_rn(a, r);
    q = __fmaf_rn(__fmaf_rn(-b, q, a), r, q);
    return q;
}

// ---------------- init -----------------------------------------------------
__global__ void k_init() {
    int idx = blockIdx.x * blockDim.x + threadIdx.x;
    if (idx < BB * 4096) g_hist1[idx] = 0u;
    if (idx < BB * 2048) g_hist2[idx] = 0u;
    if (idx < BB) {
        g_T1[idx] = SENT; g_C1[idx] = 0u;
        g_T2[idx] = 0u;   g_C2[idx] = 0u;
    }
    if (idx == 0) { g_pos = 0u; g_neg = 0u; }
}

// ---------------- main: IoU + labels + targets + keys ----------------------
__global__ void __launch_bounds__(256) k_main(
    const float4* __restrict__ anchors,   // N float4 (x0,y0,w,h)
    const float4* __restrict__ gt,        // B*G float4 (x,y,w,h)
    float* __restrict__ out)
{
    __shared__ float4 s_box[GG];    // gx0, gy0, gx1, gy1 for this batch
    __shared__ float  s_area[GG];
    __shared__ float4 s_gt0[GG];    // batch-0 raw gt (targets use gt_flat[argmax])
    const int b = blockIdx.y;
    const int t = threadIdx.x;
    const int j = blockIdx.x * 256 + t;

    if (t < GG) {
        float4 gb = gt[b * GG + t];
        s_box[t]  = make_float4(gb.x, gb.y, __fadd_rn(gb.x, gb.z), __fadd_rn(gb.y, gb.w));
        s_area[t] = __fmul_rn(gb.z, gb.w);
        s_gt0[t]  = gt[t];
    }
    __syncthreads();

    float4 a = anchors[j];
    const float ax0 = a.x, ay0 = a.y, aw = a.z, ah = a.w;
    const float ax1 = __fadd_rn(ax0, aw);
    const float ay1 = __fadd_rn(ay0, ah);
    const float aArea = __fmul_rn(aw, ah);
    const float kx1 = __fsub_rn(ax1, 1.0f);
    const float ky1 = __fsub_rn(ay1, 1.0f);
    const bool keep = (ax0 >= 0.0f) && (ay0 >= 0.0f) && (aw >= 0.0f) && (ah >= 0.0f)
                   && (ax0 <= 63.0f) && (ay0 <= 63.0f) && (kx1 <= 63.0f) && (ky1 <= 63.0f);

    float best = -1.0f;
    int   barg = 0;
    if (keep) {
#pragma unroll 4
        for (int g = 0; g < GG; g++) {
            float4 gb = s_box[g];
            float iw = fmaxf(0.0f, __fsub_rn(fminf(ax1, gb.z), fmaxf(ax0, gb.x)));
            float ih = fmaxf(0.0f, __fsub_rn(fminf(ay1, gb.w), fmaxf(ay0, gb.y)));
            float inter = __fmul_rn(iw, ih);
            float uni = __fsub_rn(__fadd_rn(aArea, s_area[g]), inter);
            float q = exact_div(inter, uni);         // inter==0 -> exactly 0
            float ov = (inter > 0.0f) ? q : 1e-10f;  // predicated select
            // (q>0 whenever inter>0 at these magnitudes, so the reference's
            //  where(ov==0, 1e-10) is already satisfied)
            bool upd = ov > best;                    // first-occurrence argmax
            best = upd ? ov : best;
            barg = upd ? g : barg;
        }
    }

    float lab;
    if (!keep)                  lab = -1.0f;
    else if (best >= 0.7f)      lab =  1.0f;
    else if (best <= 0.3f)      lab =  0.0f;
    else                        lab = -1.0f;

    const bool ispos = keep && (best > 0.7f);
    const bool isneg = keep && (best < 0.3f);
    unsigned bp = __ballot_sync(0xffffffffu, ispos);
    unsigned bn = __ballot_sync(0xffffffffu, isneg);
    if ((t & 31) == 0) {
        if (bp) atomicAdd(&g_pos, (unsigned)__popc(bp));
        if (bn) atomicAdd(&g_neg, (unsigned)__popc(bn));
    }

    const unsigned i = (unsigned)b * NN + (unsigned)j;
    unsigned key = SENT;
    if (lab == 0.0f) {
        key = rand_bits(i) >> 9;                      // 23-bit mantissa key
        atomicAdd(&g_hist1[b * 4096 + (key >> 11)], 1u);
    }
    g_key[i] = key;

    const size_t o = (size_t)i * 5;
    out[o] = lab;
    if (keep) {
        float4 g0 = s_gt0[barg];                      // reference uses batch-0 gt!
        out[o + 1] = __fsub_rn(ax0, __fmul_rn(g0.x, 0.0625f));
        out[o + 2] = __fsub_rn(ay0, __fmul_rn(g0.y, 0.0625f));
        out[o + 3] = __fsub_rn(aw,  __fmul_rn(g0.z, 0.0625f));
        out[o + 4] = __fsub_rn(ah,  __fmul_rn(g0.w, 0.0625f));
    } else {
        out[o + 1] = 0.0f; out[o + 2] = 0.0f; out[o + 3] = 0.0f; out[o + 4] = 0.0f;
    }
}

// ------------- block-wide descending cumulative select (1024 threads) ------
template <int NB>
__device__ void block_select(const unsigned* __restrict__ hist, unsigned target,
                             unsigned* out_bin, unsigned* out_before)
{
    constexpr int IT = NB / 1024;
    const int t = threadIdx.x, lane = t & 31, wid = t >> 5;
    unsigned v[IT];
    unsigned s = 0u;
#pragma unroll
    for (int q = 0; q < IT; q++) { v[q] = hist[NB - 1 - (t * IT + q)]; s += v[q]; }
    unsigned inc = s;
#pragma unroll
    for (int o = 1; o < 32; o <<= 1) {
        unsigned u = __shfl_up_sync(0xffffffffu, inc, o);
        if (lane >= o) inc += u;
    }
    __shared__ unsigned sw[32];
    if (lane == 31) sw[wid] = inc;
    __syncthreads();
    if (wid == 0) {
        unsigned w = sw[lane];
#pragma unroll
        for (int o = 1; o < 32; o <<= 1) {
            unsigned u = __shfl_up_sync(0xffffffffu, w, o);
            if (lane >= o) w += u;
        }
        sw[lane] = w;
    }
    __syncthreads();
    unsigned c = inc - s + (wid > 0 ? sw[wid - 1] : 0u);   // exclusive prefix
#pragma unroll
    for (int q = 0; q < IT; q++) {
        unsigned c2 = c + v[q];
        if (c < target && target <= c2) {
            *out_bin = (unsigned)(NB - 1 - (t * IT + q));
            *out_before = c;
        }
        c = c2;
    }
}

__device__ __forceinline__ unsigned cutoff_val() {
    unsigned c = 3u * g_pos;
    return c < 1u ? 1u : c;
}

__global__ void k_scan1() {
    const int b = blockIdx.x;
    const unsigned cutoff = cutoff_val();
    if (g_neg <= cutoff) return;                 // global gate: no disable at all
    block_select<4096>(g_hist1 + b * 4096, cutoff, &g_T1[b], &g_C1[b]);
}

__global__ void k_hist2() {
    const int b = blockIdx.y;
    const int j = blockIdx.x * 256 + threadIdx.x;
    const unsigned key = g_key[(unsigned)b * NN + j];
    if (key == SENT) return;
    if ((key >> 11) == g_T1[b])
        atomicAdd(&g_hist2[b * 2048 + (key & 2047u)], 1u);
}

__global__ void k_scan2() {
    const int b = blockIdx.x;
    const unsigned t1 = g_T1[b];
    if (t1 == SENT) return;                      // no disable in this row
    const unsigned target = cutoff_val() - g_C1[b];   // >= 1 by construction
    block_select<2048>(g_hist2 + b * 2048, target, &g_T2[b], &g_C2[b]);
}

__global__ void k_final(float* __restrict__ out) {
    const int b = blockIdx.y;
    const int j = blockIdx.x * 256 + threadIdx.x;
    const unsigned i = (unsigned)b * NN + (unsigned)j;
    const unsigned key = g_key[i];
    if (key == SENT) return;                     // not a label-0 negative
    const unsigned t1 = g_T1[b];
    if (t1 == SENT) return;                      // row survives entirely
    const unsigned Ks = (t1 << 11) | g_T2[b];
    if (key > Ks) return;                        // rank < cutoff: survives
    if (key < Ks) { out[(size_t)i * 5] = -1.0f; return; }
    // key == K*: survive only the m lowest-index ties
    const unsigned m = cutoff_val() - g_C1[b] - g_C2[b];
    const unsigned* row = g_key + (size_t)b * NN;
    unsigned cnt = 0u;
    for (int jj = 0; jj < j; jj++) cnt += (row[jj] == Ks);
    if (cnt >= m) out[(size_t)i * 5] = -1.0f;
}

// ---------------------------------------------------------------------------
extern "C" void kernel_launch(void* const* d_in, const int* in_sizes, int n_in,
                              void* d_out, int out_size)
{
    (void)in_sizes; (void)n_in; (void)out_size;
    const float4* gt      = (const float4*)d_in[1];   // (16, 64, 4)
    const float4* anchors = (const float4*)d_in[2];   // (12, 64, 64, 4) -> N float4
    float* out = (float*)d_out;

    dim3 gridBN(NN / 256, BB);
    k_init <<<256, 256>>>();
    k_main <<<gridBN, 256>>>(anchors, gt, out);
    k_scan1<<<BB, 1024>>>();
    k_hist2<<<gridBN, 256>>>();
    k_scan2<<<BB, 1024>>>();
    k_final<<<gridBN, 256>>>(out);
}

// round 8
// speedup vs baseline: 9.0673x; 9.0673x over previous
#include <cuda_runtime.h>
#include <cstdint>

// ---------------------------------------------------------------------------
// AnchorLayer: B=16, A=12, H=W=64 (N=49152/row), G=64 gt. Out (B,A,H,W,5).
// R6 (resubmit x2): remove single-address global atomics from k_main
//     (per-block partial counts + k_sum reduction); remove k_final's serial
//     tie scan (tie list + parallel k_tiefix). Init split into 3 kernels so
//     k_main sits at the ncu fixed capture offset.
// ---------------------------------------------------------------------------

#define BB   16
#define NN   49152
#define GG   64
#define TOT  (BB * NN)
#define HALF (TOT / 2)
#define SENT 0xFFFFFFFFu
#define NBLK 3072            // k_main blocks: (NN/256) * BB
#define TCAP 1024            // per-row tie-list capacity

#define TF_PARTITIONABLE 1

__device__ unsigned g_pos, g_neg;
__device__ unsigned g_ppos[NBLK], g_pneg[NBLK];
__device__ unsigned g_hist1[BB * 4096];
__device__ unsigned g_hist2[BB * 2048];
__device__ unsigned g_T1[BB], g_C1[BB];
__device__ unsigned g_T2[BB], g_C2[BB];
__device__ unsigned g_key[TOT];
__device__ unsigned g_tiecnt[BB];
__device__ unsigned g_tieidx[BB][TCAP];

// ---------------- threefry-2x32, key = (0, 42) -----------------------------
__device__ __forceinline__ unsigned tf_rotl(unsigned x, int d) {
    return (x << d) | (x >> (32 - d));
}

__device__ __forceinline__ unsigned rand_bits(unsigned i) {
    const unsigned ks0 = 0u, ks1 = 42u, ks2 = 0x1BD11BDAu ^ 0u ^ 42u;
#if TF_PARTITIONABLE
    unsigned x0 = 0u, x1 = i;
#else
    bool lo = i < HALF;
    unsigned x0 = lo ? i : i - HALF;
    unsigned x1 = lo ? i + HALF : i;
#endif
    x0 += ks0; x1 += ks1;
#define TF_R(r) { x0 += x1; x1 = tf_rotl(x1, r); x1 ^= x0; }
    TF_R(13) TF_R(15) TF_R(26) TF_R(6)
    x0 += ks1; x1 += ks2 + 1u;
    TF_R(17) TF_R(29) TF_R(16) TF_R(24)
    x0 += ks2; x1 += ks0 + 2u;
    TF_R(13) TF_R(15) TF_R(26) TF_R(6)
    x0 += ks0; x1 += ks1 + 3u;
    TF_R(17) TF_R(29) TF_R(16) TF_R(24)
    x0 += ks1; x1 += ks2 + 4u;
    TF_R(13) TF_R(15) TF_R(26) TF_R(6)
    x0 += ks2; x1 += ks0 + 5u;
#undef TF_R
#if TF_PARTITIONABLE
    return x0 ^ x1;
#else
    return lo ? x0 : x1;
#endif
}

// Branch-free correctly-rounded fp32 division (verified rel_err=0 in R5).
__device__ __forceinline__ float exact_div(float a, float b) {
    float r;
    asm("rcp.approx.f32 %0, %1;" : "=f"(r) : "f"(b));
    r = __fmaf_rn(__fmaf_rn(-b, r, 1.0f), r, r);
    r = __fmaf_rn(__fmaf_rn(-b, r, 1.0f), r, r);
    float q = __fmul_rn(a, r);
    q = __fmaf_rn(__fmaf_rn(-b, q, a), r, q);
    return q;
}

// ---------------- init (3 kernels so k_main is 4th launch) -----------------
__global__ void k_init_a() {      // zero hist1 (65536)
    g_hist1[blockIdx.x * 256 + threadIdx.x] = 0u;
}
__global__ void k_init_b() {      // zero hist2 (32768)
    g_hist2[blockIdx.x * 256 + threadIdx.x] = 0u;
}
__global__ void k_init_c() {      // small state
    int idx = threadIdx.x;
    if (idx < BB) {
        g_T1[idx] = SENT; g_C1[idx] = 0u;
        g_T2[idx] = 0u;   g_C2[idx] = 0u;
        g_tiecnt[idx] = 0u;
    }
    if (idx == 0) { g_pos = 0u; g_neg = 0u; }
}

// ---------------- main: IoU + labels + targets + keys ----------------------
__global__ void __launch_bounds__(256) k_main(
    const float4* __restrict__ anchors,
    const float4* __restrict__ gt,
    float* __restrict__ out)
{
    __shared__ float4 s_box[GG];
    __shared__ float  s_area[GG];
    __shared__ float4 s_gt0[GG];
    __shared__ unsigned s_pos[8], s_neg[8];
    const int b = blockIdx.y;
    const int t = threadIdx.x;
    const int j = blockIdx.x * 256 + t;

    if (t < GG) {
        float4 gb = gt[b * GG + t];
        s_box[t]  = make_float4(gb.x, gb.y, __fadd_rn(gb.x, gb.z), __fadd_rn(gb.y, gb.w));
        s_area[t] = __fmul_rn(gb.z, gb.w);
        s_gt0[t]  = gt[t];
    }
    __syncthreads();

    float4 a = anchors[j];
    const float ax0 = a.x, ay0 = a.y, aw = a.z, ah = a.w;
    const float ax1 = __fadd_rn(ax0, aw);
    const float ay1 = __fadd_rn(ay0, ah);
    const float aArea = __fmul_rn(aw, ah);
    const float kx1 = __fsub_rn(ax1, 1.0f);
    const float ky1 = __fsub_rn(ay1, 1.0f);
    const bool keep = (ax0 >= 0.0f) && (ay0 >= 0.0f) && (aw >= 0.0f) && (ah >= 0.0f)
                   && (ax0 <= 63.0f) && (ay0 <= 63.0f) && (kx1 <= 63.0f) && (ky1 <= 63.0f);

    float best = -1.0f;
    int   barg = 0;
    if (keep) {
#pragma unroll 4
        for (int g = 0; g < GG; g++) {
            float4 gb = s_box[g];
            float iw = fmaxf(0.0f, __fsub_rn(fminf(ax1, gb.z), fmaxf(ax0, gb.x)));
            float ih = fmaxf(0.0f, __fsub_rn(fminf(ay1, gb.w), fmaxf(ay0, gb.y)));
            float inter = __fmul_rn(iw, ih);
            float uni = __fsub_rn(__fadd_rn(aArea, s_area[g]), inter);
            float q = exact_div(inter, uni);
            float ov = (inter > 0.0f) ? q : 1e-10f;
            bool upd = ov > best;
            best = upd ? ov : best;
            barg = upd ? g : barg;
        }
    }

    float lab;
    if (!keep)                  lab = -1.0f;
    else if (best >= 0.7f)      lab =  1.0f;
    else if (best <= 0.3f)      lab =  0.0f;
    else                        lab = -1.0f;

    // per-block pos/neg partial counts (NO single-address global atomics)
    const bool ispos = keep && (best > 0.7f);
    const bool isneg = keep && (best < 0.3f);
    unsigned bp = __ballot_sync(0xffffffffu, ispos);
    unsigned bn = __ballot_sync(0xffffffffu, isneg);
    if ((t & 31) == 0) { s_pos[t >> 5] = (unsigned)__popc(bp); s_neg[t >> 5] = (unsigned)__popc(bn); }
    __syncthreads();
    if (t == 0) {
        unsigned p = 0u, n = 0u;
#pragma unroll
        for (int w = 0; w < 8; w++) { p += s_pos[w]; n += s_neg[w]; }
        const int bf = b * gridDim.x + blockIdx.x;
        g_ppos[bf] = p; g_pneg[bf] = n;
    }

    const unsigned i = (unsigned)b * NN + (unsigned)j;
    unsigned key = SENT;
    if (lab == 0.0f) {
        key = rand_bits(i) >> 9;
        atomicAdd(&g_hist1[b * 4096 + (key >> 11)], 1u);   // spread addresses: OK
    }
    g_key[i] = key;

    const size_t o = (size_t)i * 5;
    out[o] = lab;
    if (keep) {
        float4 g0 = s_gt0[barg];
        out[o + 1] = __fsub_rn(ax0, __fmul_rn(g0.x, 0.0625f));
        out[o + 2] = __fsub_rn(ay0, __fmul_rn(g0.y, 0.0625f));
        out[o + 3] = __fsub_rn(aw,  __fmul_rn(g0.z, 0.0625f));
        out[o + 4] = __fsub_rn(ah,  __fmul_rn(g0.w, 0.0625f));
    } else {
        out[o + 1] = 0.0f; out[o + 2] = 0.0f; out[o + 3] = 0.0f; out[o + 4] = 0.0f;
    }
}

// ---------------- sum partials -> g_pos/g_neg ------------------------------
__global__ void k_sum() {
    const int t = threadIdx.x, lane = t & 31, wid = t >> 5;
    unsigned p = 0u, n = 0u;
    for (int i = t; i < NBLK; i += 1024) { p += g_ppos[i]; n += g_pneg[i]; }
#pragma unroll
    for (int o = 16; o; o >>= 1) {
        p += __shfl_down_sync(0xffffffffu, p, o);
        n += __shfl_down_sync(0xffffffffu, n, o);
    }
    __shared__ unsigned sp[32], sn[32];
    if (lane == 0) { sp[wid] = p; sn[wid] = n; }
    __syncthreads();
    if (wid == 0) {
        p = sp[lane]; n = sn[lane];
#pragma unroll
        for (int o = 16; o; o >>= 1) {
            p += __shfl_down_sync(0xffffffffu, p, o);
            n += __shfl_down_sync(0xffffffffu, n, o);
        }
        if (lane == 0) { g_pos = p; g_neg = n; }
    }
}

// ------------- block-wide descending cumulative select ---------------------
template <int NB>
__device__ void block_select(const unsigned* __restrict__ hist, unsigned target,
                             unsigned* out_bin, unsigned* out_before)
{
    constexpr int IT = NB / 1024;
    const int t = threadIdx.x, lane = t & 31, wid = t >> 5;
    unsigned v[IT];
    unsigned s = 0u;
#pragma unroll
    for (int q = 0; q < IT; q++) { v[q] = hist[NB - 1 - (t * IT + q)]; s += v[q]; }
    unsigned inc = s;
#pragma unroll
    for (int o = 1; o < 32; o <<= 1) {
        unsigned u = __shfl_up_sync(0xffffffffu, inc, o);
        if (lane >= o) inc += u;
    }
    __shared__ unsigned sw[32];
    if (lane == 31) sw[wid] = inc;
    __syncthreads();
    if (wid == 0) {
        unsigned w = sw[lane];
#pragma unroll
        for (int o = 1; o < 32; o <<= 1) {
            unsigned u = __shfl_up_sync(0xffffffffu, w, o);
            if (lane >= o) w += u;
        }
        sw[lane] = w;
    }
    __syncthreads();
    unsigned c = inc - s + (wid > 0 ? sw[wid - 1] : 0u);
#pragma unroll
    for (int q = 0; q < IT; q++) {
        unsigned c2 = c + v[q];
        if (c < target && target <= c2) {
            *out_bin = (unsigned)(NB - 1 - (t * IT + q));
            *out_before = c;
        }
        c = c2;
    }
}

__device__ __forceinline__ unsigned cutoff_val() {
    unsigned c = 3u * g_pos;
    return c < 1u ? 1u : c;
}

__global__ void k_scan1() {
    const int b = blockIdx.x;
    const unsigned cutoff = cutoff_val();
    if (g_neg <= cutoff) return;
    block_select<4096>(g_hist1 + b * 4096, cutoff, &g_T1[b], &g_C1[b]);
}

__global__ void k_hist2() {
    const int b = blockIdx.y;
    const int j = blockIdx.x * 256 + threadIdx.x;
    const unsigned key = g_key[(unsigned)b * NN + j];
    if (key == SENT) return;
    if ((key >> 11) == g_T1[b])
        atomicAdd(&g_hist2[b * 2048 + (key & 2047u)], 1u);
}

__global__ void k_scan2() {
    const int b = blockIdx.x;
    const unsigned t1 = g_T1[b];
    if (t1 == SENT) return;
    const unsigned target = cutoff_val() - g_C1[b];
    block_select<2048>(g_hist2 + b * 2048, target, &g_T2[b], &g_C2[b]);
}

// Disable key<Ks; collect key==Ks into per-row tie list (rank resolved later)
__global__ void k_final(float* __restrict__ out) {
    const int b = blockIdx.y;
    const int j = blockIdx.x * 256 + threadIdx.x;
    const unsigned i = (unsigned)b * NN + (unsigned)j;
    const unsigned key = g_key[i];
    if (key == SENT) return;
    const unsigned t1 = g_T1[b];
    if (t1 == SENT) return;
    const unsigned Ks = (t1 << 11) | g_T2[b];
    if (key > Ks) return;
    if (key < Ks) { out[(size_t)i * 5] = -1.0f; return; }
    unsigned slot = atomicAdd(&g_tiecnt[b], 1u);     // per-row, ~1-3 ops total
    if (slot < TCAP) g_tieidx[b][slot] = (unsigned)j;
}

// Resolve index-order ranks among ties; disable rank >= m
__global__ void k_tiefix(float* __restrict__ out) {
    const int b = blockIdx.x;
    const unsigned t1 = g_T1[b];
    if (t1 == SENT) return;
    unsigned E = g_tiecnt[b];
    if (E > TCAP) E = TCAP;
    const unsigned m = cutoff_val() - g_C1[b] - g_C2[b];
    for (unsigned e = threadIdx.x; e < E; e += blockDim.x) {
        const unsigned je = g_tieidx[b][e];
        unsigned cnt = 0u;
        for (unsigned o = 0; o < E; o++) cnt += (g_tieidx[b][o] < je);
        if (cnt >= m) out[((size_t)b * NN + je) * 5] = -1.0f;
    }
}

// ---------------------------------------------------------------------------
extern "C" void kernel_launch(void* const* d_in, const int* in_sizes, int n_in,
                              void* d_out, int out_size)
{
    (void)in_sizes; (void)n_in; (void)out_size;
    const float4* gt      = (const float4*)d_in[1];
    const float4* anchors = (const float4*)d_in[2];
    float* out = (float*)d_out;

    dim3 gridBN(NN / 256, BB);
    k_init_a<<<256, 256>>>();
    k_init_b<<<128, 256>>>();
    k_init_c<<<1, 64>>>();
    k_main  <<<gridBN, 256>>>(anchors, gt, out);   // 4th launch -> ncu window
    k_sum   <<<1, 1024>>>();
    k_scan1 <<<BB, 1024>>>();
    k_hist2 <<<gridBN, 256>>>();
    k_scan2 <<<BB, 1024>>>();
    k_final <<<gridBN, 256>>>(out);
    k_tiefix<<<BB, 256>>>(out);
}

// round 13
// speedup vs baseline: 15.2481x; 1.6817x over previous
#include <cuda_runtime.h>
#include <cstdint>

// ---------------------------------------------------------------------------
// AnchorLayer: B=16, A=12, H=W=64 (N=49152/row), G=64 gt. Out (B,A,H,W,5).
// R13 = R9 y-cull + fold k_sum into k_scan1 (launch count 10 -> 9).
//   - y-cull: block = one anchor type (fixed hs) x 4 h-rows x 64 w; only gt
//     whose y-interval intersects the block band can give ih>0; ballot-compact
//     ~20-24 candidates and loop over those (R8: k_main 56us issue-bound).
//   - k_scan1 blocks redundantly sum g_ppos/g_pneg (exact, order-independent)
//     and publish g_pos/g_neg; removes the k_sum launch, zero semantic risk.
// ---------------------------------------------------------------------------

#define BB   16
#define NN   49152
#define GG   64
#define TOT  (BB * NN)
#define HALF (TOT / 2)
#define SENT 0xFFFFFFFFu
#define NBLK 3072            // k_main blocks: (NN/256) * BB
#define TCAP 1024            // per-row tie-list capacity

#define TF_PARTITIONABLE 1

__device__ unsigned g_pos, g_neg;
__device__ unsigned g_ppos[NBLK], g_pneg[NBLK];
__device__ unsigned g_hist1[BB * 4096];
__device__ unsigned g_hist2[BB * 2048];
__device__ unsigned g_T1[BB], g_C1[BB];
__device__ unsigned g_T2[BB], g_C2[BB];
__device__ unsigned g_key[TOT];
__device__ unsigned g_tiecnt[BB];
__device__ unsigned g_tieidx[BB][TCAP];

// ---------------- threefry-2x32, key = (0, 42) -----------------------------
__device__ __forceinline__ unsigned tf_rotl(unsigned x, int d) {
    return (x << d) | (x >> (32 - d));
}

__device__ __forceinline__ unsigned rand_bits(unsigned i) {
    const unsigned ks0 = 0u, ks1 = 42u, ks2 = 0x1BD11BDAu ^ 0u ^ 42u;
#if TF_PARTITIONABLE
    unsigned x0 = 0u, x1 = i;
#else
    bool lo = i < HALF;
    unsigned x0 = lo ? i : i - HALF;
    unsigned x1 = lo ? i + HALF : i;
#endif
    x0 += ks0; x1 += ks1;
#define TF_R(r) { x0 += x1; x1 = tf_rotl(x1, r); x1 ^= x0; }
    TF_R(13) TF_R(15) TF_R(26) TF_R(6)
    x0 += ks1; x1 += ks2 + 1u;
    TF_R(17) TF_R(29) TF_R(16) TF_R(24)
    x0 += ks2; x1 += ks0 + 2u;
    TF_R(13) TF_R(15) TF_R(26) TF_R(6)
    x0 += ks0; x1 += ks1 + 3u;
    TF_R(17) TF_R(29) TF_R(16) TF_R(24)
    x0 += ks1; x1 += ks2 + 4u;
    TF_R(13) TF_R(15) TF_R(26) TF_R(6)
    x0 += ks2; x1 += ks0 + 5u;
#undef TF_R
#if TF_PARTITIONABLE
    return x0 ^ x1;
#else
    return lo ? x0 : x1;
#endif
}

// Branch-free correctly-rounded fp32 division (verified rel_err=0 twice).
__device__ __forceinline__ float exact_div(float a, float b) {
    float r;
    asm("rcp.approx.f32 %0, %1;" : "=f"(r) : "f"(b));
    r = __fmaf_rn(__fmaf_rn(-b, r, 1.0f), r, r);
    r = __fmaf_rn(__fmaf_rn(-b, r, 1.0f), r, r);
    float q = __fmul_rn(a, r);
    q = __fmaf_rn(__fmaf_rn(-b, q, a), r, q);
    return q;
}

// ---------------- init (3 kernels so k_main keeps its ncu slot) ------------
__global__ void k_init_a() {      // zero hist1 (65536)
    g_hist1[blockIdx.x * 256 + threadIdx.x] = 0u;
}
__global__ void k_init_b() {      // zero hist2 (32768)
    g_hist2[blockIdx.x * 256 + threadIdx.x] = 0u;
}
__global__ void k_init_c() {      // small state
    int idx = threadIdx.x;
    if (idx < BB) {
        g_T1[idx] = SENT; g_C1[idx] = 0u;
        g_T2[idx] = 0u;   g_C2[idx] = 0u;
        g_tiecnt[idx] = 0u;
    }
    if (idx == 0) { g_pos = 0u; g_neg = 0u; }
}

// ---------------- main: IoU + labels + targets + keys ----------------------
__global__ void __launch_bounds__(256) k_main(
    const float4* __restrict__ anchors,
    const float4* __restrict__ gt,
    float* __restrict__ out)
{
    __shared__ float4 s_box[GG];     // gx0, gy0, gx1, gy1
    __shared__ float  s_area[GG];
    __shared__ float4 s_gt0[GG];     // batch-0 raw gt (targets use gt_flat[argmax])
    __shared__ float4 s_cbox[GG];    // culled candidates
    __shared__ float  s_carea[GG];
    __shared__ int    s_cg[GG];
    __shared__ float  s_ymin, s_ymax;
    __shared__ int    s_cnt;
    __shared__ unsigned s_pos[8], s_neg[8];
    const int b = blockIdx.y;
    const int t = threadIdx.x;
    const int j = blockIdx.x * 256 + t;

    if (t < GG) {
        float4 gb = gt[b * GG + t];
        s_box[t]  = make_float4(gb.x, gb.y, __fadd_rn(gb.x, gb.z), __fadd_rn(gb.y, gb.w));
        s_area[t] = __fmul_rn(gb.z, gb.w);
        s_gt0[t]  = gt[t];
    }
    if (t == 0) {
        // block = one anchor type (fixed hs) x 4 h-rows x 64 w
        float4 afirst = anchors[blockIdx.x * 256];         // row h0 anchor
        float4 alast  = anchors[blockIdx.x * 256 + 192];   // row h0+3 anchor
        s_ymin = afirst.y;                                 // min ay0 in block
        s_ymax = __fadd_rn(alast.y, alast.w);              // max ay1 in block
    }
    __syncthreads();

    // --- gt y-cull + ballot compaction (warps 0-1) ---
    if (t < GG) {
        const int lane = t & 31, wid = t >> 5;
        // necessary condition for ih>0 with ANY anchor in this block
        bool pass = (s_box[t].w > s_ymin) && (s_box[t].y < s_ymax);
        unsigned bal = __ballot_sync(0xffffffffu, pass);
        if (lane == 0) s_pos[wid] = bal;    // publish per-warp ballots
    }
    __syncthreads();
    if (t < GG) {
        const int lane = t & 31, wid = t >> 5;
        unsigned bal = s_pos[wid];
        bool pass = (bal >> lane) & 1u;
        if (pass) {
            int pos = __popc(bal & ((1u << lane) - 1u));
            if (wid == 1) pos += __popc(s_pos[0]);
            s_cbox[pos]  = s_box[t];
            s_carea[pos] = s_area[t];
            s_cg[pos]    = t;
        }
        if (t == 0) s_cnt = __popc(s_pos[0]) + __popc(s_pos[1]);
    }
    __syncthreads();
    const int K = s_cnt;

    float4 a = anchors[j];
    const float ax0 = a.x, ay0 = a.y, aw = a.z, ah = a.w;
    const float ax1 = __fadd_rn(ax0, aw);
    const float ay1 = __fadd_rn(ay0, ah);
    const float aArea = __fmul_rn(aw, ah);
    const float kx1 = __fsub_rn(ax1, 1.0f);
    const float ky1 = __fsub_rn(ay1, 1.0f);
    const bool keep = (ax0 >= 0.0f) && (ay0 >= 0.0f) && (aw >= 0.0f) && (ah >= 0.0f)
                   && (ax0 <= 63.0f) && (ay0 <= 63.0f) && (kx1 <= 63.0f) && (ky1 <= 63.0f);

    // best init 1e-10 / barg 0: skipped gts contribute exactly 1e-10 and can
    // never win a strict '>' -> identical to full argmax (first occurrence).
    float best = 1e-10f;
    int   barg = 0;
    if (keep) {
#pragma unroll 4
        for (int c = 0; c < K; c++) {
            float4 gb = s_cbox[c];
            float iw = fmaxf(0.0f, __fsub_rn(fminf(ax1, gb.z), fmaxf(ax0, gb.x)));
            float ih = fmaxf(0.0f, __fsub_rn(fminf(ay1, gb.w), fmaxf(ay0, gb.y)));
            float inter = __fmul_rn(iw, ih);
            float uni = __fsub_rn(__fadd_rn(aArea, s_carea[c]), inter);
            float q = exact_div(inter, uni);
            float ov = (inter > 0.0f) ? q : 1e-10f;
            bool upd = ov > best;
            best = upd ? ov : best;
            barg = upd ? s_cg[c] : barg;
        }
    }

    float lab;
    if (!keep)                  lab = -1.0f;
    else if (best >= 0.7f)      lab =  1.0f;
    else if (best <= 0.3f)      lab =  0.0f;
    else                        lab = -1.0f;

    // per-block pos/neg partial counts (no single-address global atomics)
    const bool ispos = keep && (best > 0.7f);
    const bool isneg = keep && (best < 0.3f);
    unsigned bp = __ballot_sync(0xffffffffu, ispos);
    unsigned bn = __ballot_sync(0xffffffffu, isneg);
    __syncthreads();   // s_pos was reused for ballots above; re-sync before reuse
    if ((t & 31) == 0) { s_pos[t >> 5] = (unsigned)__popc(bp); s_neg[t >> 5] = (unsigned)__popc(bn); }
    __syncthreads();
    if (t == 0) {
        unsigned p = 0u, n = 0u;
#pragma unroll
        for (int w = 0; w < 8; w++) { p += s_pos[w]; n += s_neg[w]; }
        const int bf = b * gridDim.x + blockIdx.x;
        g_ppos[bf] = p; g_pneg[bf] = n;
    }

    const unsigned i = (unsigned)b * NN + (unsigned)j;
    unsigned key = SENT;
    if (lab == 0.0f) {
        key = rand_bits(i) >> 9;
        atomicAdd(&g_hist1[b * 4096 + (key >> 11)], 1u);   // spread addresses: OK
    }
    g_key[i] = key;

    const size_t o = (size_t)i * 5;
    out[o] = lab;
    if (keep) {
        float4 g0 = s_gt0[barg];
        out[o + 1] = __fsub_rn(ax0, __fmul_rn(g0.x, 0.0625f));
        out[o + 2] = __fsub_rn(ay0, __fmul_rn(g0.y, 0.0625f));
        out[o + 3] = __fsub_rn(aw,  __fmul_rn(g0.z, 0.0625f));
        out[o + 4] = __fsub_rn(ah,  __fmul_rn(g0.w, 0.0625f));
    } else {
        out[o + 1] = 0.0f; out[o + 2] = 0.0f; out[o + 3] = 0.0f; out[o + 4] = 0.0f;
    }
}

// ------------- block-wide descending cumulative select ---------------------
template <int NB>
__device__ void block_select(const unsigned* __restrict__ hist, unsigned target,
                             unsigned* out_bin, unsigned* out_before)
{
    constexpr int IT = NB / 1024;
    const int t = threadIdx.x, lane = t & 31, wid = t >> 5;
    unsigned v[IT];
    unsigned s = 0u;
#pragma unroll
    for (int q = 0; q < IT; q++) { v[q] = hist[NB - 1 - (t * IT + q)]; s += v[q]; }
    unsigned inc = s;
#pragma unroll
    for (int o = 1; o < 32; o <<= 1) {
        unsigned u = __shfl_up_sync(0xffffffffu, inc, o);
        if (lane >= o) inc += u;
    }
    __shared__ unsigned sw[32];
    if (lane == 31) sw[wid] = inc;
    __syncthreads();
    if (wid == 0) {
        unsigned w = sw[lane];
#pragma unroll
        for (int o = 1; o < 32; o <<= 1) {
            unsigned u = __shfl_up_sync(0xffffffffu, w, o);
            if (lane >= o) w += u;
        }
        sw[lane] = w;
    }
    __syncthreads();
    unsigned c = inc - s + (wid > 0 ? sw[wid - 1] : 0u);
#pragma unroll
    for (int q = 0; q < IT; q++) {
        unsigned c2 = c + v[q];
        if (c < target && target <= c2) {
            *out_bin = (unsigned)(NB - 1 - (t * IT + q));
            *out_before = c;
        }
        c = c2;
    }
}

__device__ __forceinline__ unsigned cutoff_val() {
    unsigned c = 3u * g_pos;
    return c < 1u ? 1u : c;
}

// k_scan1 now also performs the partial-count reduction (ex-k_sum): every
// block computes the identical exact sums and publishes g_pos/g_neg (benign
// same-value writes), then proceeds with the descending select.
__global__ void k_scan1() {
    const int b = blockIdx.x;
    const int t = threadIdx.x, lane = t & 31, wid = t >> 5;

    unsigned p = 0u, n = 0u;
    for (int i = t; i < NBLK; i += 1024) { p += g_ppos[i]; n += g_pneg[i]; }
#pragma unroll
    for (int o = 16; o; o >>= 1) {
        p += __shfl_down_sync(0xffffffffu, p, o);
        n += __shfl_down_sync(0xffffffffu, n, o);
    }
    __shared__ unsigned sp[32], sn[32];
    __shared__ unsigned s_p, s_n;
    if (lane == 0) { sp[wid] = p; sn[wid] = n; }
    __syncthreads();
    if (wid == 0) {
        p = sp[lane]; n = sn[lane];
#pragma unroll
        for (int o = 16; o; o >>= 1) {
            p += __shfl_down_sync(0xffffffffu, p, o);
            n += __shfl_down_sync(0xffffffffu, n, o);
        }
        if (lane == 0) {
            s_p = p; s_n = n;
            g_pos = p; g_neg = n;     // same value from every block: benign
        }
    }
    __syncthreads();
    const unsigned pos = s_p, neg = s_n;
    unsigned cutoff = 3u * pos; if (cutoff < 1u) cutoff = 1u;
    if (neg <= cutoff) return;                 // no disable at all
    block_select<4096>(g_hist1 + b * 4096, cutoff, &g_T1[b], &g_C1[b]);
}

__global__ void k_hist2() {
    const int b = blockIdx.y;
    const int j = blockIdx.x * 256 + threadIdx.x;
    const unsigned key = g_key[(unsigned)b * NN + j];
    if (key == SENT) return;
    if ((key >> 11) == g_T1[b])
        atomicAdd(&g_hist2[b * 2048 + (key & 2047u)], 1u);
}

__global__ void k_scan2() {
    const int b = blockIdx.x;
    const unsigned t1 = g_T1[b];
    if (t1 == SENT) return;
    const unsigned target = cutoff_val() - g_C1[b];
    block_select<2048>(g_hist2 + b * 2048, target, &g_T2[b], &g_C2[b]);
}

// Disable key<Ks; collect key==Ks into per-row tie list (rank resolved later)
__global__ void k_final(float* __restrict__ out) {
    const int b = blockIdx.y;
    const int j = blockIdx.x * 256 + threadIdx.x;
    const unsigned i = (unsigned)b * NN + (unsigned)j;
    const unsigned key = g_key[i];
    if (key == SENT) return;
    const unsigned t1 = g_T1[b];
    if (t1 == SENT) return;
    const unsigned Ks = (t1 << 11) | g_T2[b];
    if (key > Ks) return;
    if (key < Ks) { out[(size_t)i * 5] = -1.0f; return; }
    unsigned slot = atomicAdd(&g_tiecnt[b], 1u);     // per-row, ~1-3 ops total
    if (slot < TCAP) g_tieidx[b][slot] = (unsigned)j;
}

// Resolve index-order ranks among ties; disable rank >= m
__global__ void k_tiefix(float* __restrict__ out) {
    const int b = blockIdx.x;
    const unsigned t1 = g_T1[b];
    if (t1 == SENT) return;
    unsigned E = g_tiecnt[b];
    if (E > TCAP) E = TCAP;
    const unsigned m = cutoff_val() - g_C1[b] - g_C2[b];
    for (unsigned e = threadIdx.x; e < E; e += blockDim.x) {
        const unsigned je = g_tieidx[b][e];
        unsigned cnt = 0u;
        for (unsigned o = 0; o < E; o++) cnt += (g_tieidx[b][o] < je);
        if (cnt >= m) out[((size_t)b * NN + je) * 5] = -1.0f;
    }
}

// ---------------------------------------------------------------------------
extern "C" void kernel_launch(void* const* d_in, const int* in_sizes, int n_in,
                              void* d_out, int out_size)
{
    (void)in_sizes; (void)n_in; (void)out_size;
    const float4* gt      = (const float4*)d_in[1];
    const float4* anchors = (const float4*)d_in[2];
    float* out = (float*)d_out;

    dim3 gridBN(NN / 256, BB);
    k_init_a<<<256, 256>>>();
    k_init_b<<<128, 256>>>();
    k_init_c<<<1, 64>>>();
    k_main  <<<gridBN, 256>>>(anchors, gt, out);   // keeps ncu capture slot
    k_scan1 <<<BB, 1024>>>();                      // includes ex-k_sum reduce
    k_hist2 <<<gridBN, 256>>>();
    k_scan2 <<<BB, 1024>>>();
    k_final <<<gridBN, 256>>>(out);
    k_tiefix<<<BB, 256>>>(out);
}